// round 12
// baseline (speedup 1.0000x reference)
#include <cuda_runtime.h>
#include <cuda_bf16.h>
#include <cstdint>

#define NROWS 1048576
#define DIM   128
#define NSEG  4096

// Scratch (__device__ globals per allocation-free rule)
__device__ float g_xs[NSEG * DIM];                          // segment sums (2 MB)
__device__ float g_xm[NSEG * DIM];                          // xs @ Lambda^T (2 MB)
__device__ __align__(16) __nv_bfloat16 g_GbI[DIM * 136];    // Gamma bf16, padded-row image

#define ASTRIDE 136                         // halves per smem row (pad 8)
#define K3_SMEM (2 * 128 * ASTRIDE * 2)     // 69632 bytes
#define EPI_STRIDE 132                      // floats; 128*132*4 = 67584 <= 69632

__device__ __forceinline__ uint32_t smem_u32(const void* p) {
    uint32_t a;
    asm("{ .reg .u64 t; cvta.to.shared.u64 t, %1; cvt.u32.u64 %0, t; }" : "=r"(a) : "l"(p));
    return a;
}
__device__ __forceinline__ uint32_t pack_bf16x2(float lo, float hi) {
    uint32_t r;
    asm("cvt.rn.bf16x2.f32 %0, %1, %2;" : "=r"(r) : "f"(hi), "f"(lo));
    return r;
}
__device__ __forceinline__ float4 ldcs_f4(const float* p) {
    float4 v;
    asm volatile("ld.global.cs.v4.f32 {%0,%1,%2,%3}, [%4];"
                 : "=f"(v.x), "=f"(v.y), "=f"(v.z), "=f"(v.w) : "l"(p));
    return v;
}
__device__ __forceinline__ void stcs_f4(float* p, float4 v) {
    asm volatile("st.global.cs.v4.f32 [%0], {%1,%2,%3,%4};"
                 :: "l"(p), "f"(v.x), "f"(v.y), "f"(v.z), "f"(v.w) : "memory");
}

// ---------------------------------------------------------------------------
// Kernel 0: zero g_xs, build padded-row bf16 image of Gamma [n][k]
// ---------------------------------------------------------------------------
__global__ void k0_init(const float* __restrict__ GW) {
    int idx = blockIdx.x * blockDim.x + threadIdx.x;
    if (idx < NSEG * DIM) g_xs[idx] = 0.0f;
    if (idx < DIM * DIM) {
        int n = idx >> 7, k = idx & 127;
        g_GbI[n * ASTRIDE + k] = __float2bfloat16(GW[idx]);
    }
}

// ---------------------------------------------------------------------------
// Kernel 1: segment sum (sorted ids). Explicit 8-wide load batching + .cs.
// ---------------------------------------------------------------------------
__global__ __launch_bounds__(256) void k1_segsum(const float* __restrict__ x,
                                                 const int* __restrict__ seg) {
    int t = threadIdx.x;
    int stream = t >> 5;
    int c = (t & 31) * 4;
    int base = blockIdx.x * 1024 + stream;

    float4 acc = make_float4(0.f, 0.f, 0.f, 0.f);
    int cur = seg[base];

    for (int ii = 0; ii < 16; ii++) {
        int s8[8];
        float4 v8[8];
        #pragma unroll
        for (int j = 0; j < 8; j++) {
            int r = base + (ii * 8 + j) * 8;
            s8[j] = seg[r];
            v8[j] = ldcs_f4(x + (size_t)r * DIM + c);
        }
        #pragma unroll
        for (int j = 0; j < 8; j++) {
            if (s8[j] != cur) {
                float* d = g_xs + (size_t)cur * DIM + c;
                atomicAdd(d + 0, acc.x); atomicAdd(d + 1, acc.y);
                atomicAdd(d + 2, acc.z); atomicAdd(d + 3, acc.w);
                acc = make_float4(0.f, 0.f, 0.f, 0.f);
                cur = s8[j];
            }
            acc.x += v8[j].x; acc.y += v8[j].y;
            acc.z += v8[j].z; acc.w += v8[j].w;
        }
    }
    float* d = g_xs + (size_t)cur * DIM + c;
    atomicAdd(d + 0, acc.x); atomicAdd(d + 1, acc.y);
    atomicAdd(d + 2, acc.z); atomicAdd(d + 3, acc.w);
}

// ---------------------------------------------------------------------------
// Kernel 2: g_xm = g_xs @ Lambda_W^T (fp32 exact)
// ---------------------------------------------------------------------------
__global__ __launch_bounds__(128) void k2_xm(const float* __restrict__ LW) {
    extern __shared__ float sm2[];
    float* Lt  = sm2;                 // [128][129]
    float* xss = sm2 + 128 * 129;     // [16][128]
    int t = threadIdx.x;
    int R0 = blockIdx.x * 16;

    for (int i = 0; i < 128; i++) {
        int e = i * 128 + t;
        int j = e >> 7, k = e & 127;
        Lt[k * 129 + j] = LW[e];
    }
    for (int i = 0; i < 16; i++) {
        int e = i * 128 + t;
        int r = e >> 7, k = e & 127;
        xss[r * 128 + k] = g_xs[(size_t)(R0 + r) * DIM + k];
    }
    __syncthreads();

    float acc[16];
    #pragma unroll
    for (int r = 0; r < 16; r++) acc[r] = 0.f;
    for (int k = 0; k < 128; k++) {
        float lv = Lt[k * 129 + t];
        #pragma unroll
        for (int r = 0; r < 16; r++) acc[r] += xss[r * 128 + k] * lv;
    }
    #pragma unroll
    for (int r = 0; r < 16; r++)
        g_xm[(size_t)(R0 + r) * DIM + t] = acc[r];
}

// ---------------------------------------------------------------------------
// Kernel 3: out = x @ Gamma^T (bf16 HMMA) + bias - xm[seg]
// R10 mainloop + NEW transposed epilogue: raw acc -> smem (reusing A/B tile
// space), then warp-owns-row phase: seg broadcast, coalesced xm/bias loads,
// st.global.cs.v4 full-row stores (4 lines/instr vs 8 lines per 8B store).
// ---------------------------------------------------------------------------
__global__ __launch_bounds__(256, 2) void k3_main(const float* __restrict__ x,
                                                  const int* __restrict__ seg,
                                                  const float* __restrict__ bias,
                                                  float* __restrict__ out) {
    extern __shared__ __nv_bfloat16 sm3[];
    __nv_bfloat16* As = sm3;                       // [128][136]
    __nv_bfloat16* Bs = sm3 + 128 * ASTRIDE;       // [128][136]  Bs[n][k]
    float* epi = (float*)sm3;                      // reused after MMA: [128][132]

    int tid  = threadIdx.x;
    int warp = tid >> 5;
    int lane = tid & 31;
    int r0 = blockIdx.x * 128;
    int m0 = (warp & 3) * 32;
    int n0 = (warp >> 2) * 64;
    uint32_t sbB = smem_u32(Bs);
    uint32_t sbA = smem_u32(As);

    // Stage B via flat cp.async of padded image (34816 B)
    #pragma unroll
    for (int i = 0; i < 9; i++) {
        int e = i * 256 + tid;
        if (e < (128 * ASTRIDE * 2) / 16)
            asm volatile("cp.async.cg.shared.global [%0], [%1], 16;"
                         :: "r"(sbB + e * 16),
                            "l"((const char*)g_GbI + e * 16) : "memory");
    }
    asm volatile("cp.async.commit_group;" ::: "memory");

    // Stage A: LDG.cs fp32 -> bf16 -> STS.128
    #pragma unroll
    for (int i = 0; i < 8; i++) {
        int e = i * 256 + tid;
        int row = e >> 4, g2 = e & 15;
        const float* src = x + (size_t)(r0 + row) * DIM + g2 * 8;
        float4 v0 = ldcs_f4(src);
        float4 v1 = ldcs_f4(src + 4);
        uint32_t p0 = pack_bf16x2(v0.x, v0.y);
        uint32_t p1 = pack_bf16x2(v0.z, v0.w);
        uint32_t p2 = pack_bf16x2(v1.x, v1.y);
        uint32_t p3 = pack_bf16x2(v1.z, v1.w);
        asm volatile("st.shared.v4.b32 [%0], {%1,%2,%3,%4};"
                     :: "r"(sbA + (row * ASTRIDE + g2 * 8) * 2),
                        "r"(p0), "r"(p1), "r"(p2), "r"(p3) : "memory");
    }

    asm volatile("cp.async.wait_group 0;" ::: "memory");
    __syncthreads();

    int g  = lane >> 2;
    int t4 = lane & 3;

    // Fragment base addresses
    uint32_t aoff[2];
    #pragma unroll
    for (int mt = 0; mt < 2; mt++)
        aoff[mt] = sbA + ((m0 + mt * 16 + (lane & 15)) * ASTRIDE + ((lane >> 4) << 3)) * 2;
    uint32_t boff = sbB + ((n0 + (lane & 7) + ((lane >> 4) << 3)) * ASTRIDE
                           + (((lane >> 3) & 1) << 3)) * 2;

    float acc[2][8][4];
    #pragma unroll
    for (int mt = 0; mt < 2; mt++)
        #pragma unroll
        for (int nt = 0; nt < 8; nt++)
            #pragma unroll
            for (int q = 0; q < 4; q++) acc[mt][nt][q] = 0.f;

    #pragma unroll
    for (int ks = 0; ks < 8; ks++) {
        uint32_t a[2][4], b[4][4];
        #pragma unroll
        for (int mt = 0; mt < 2; mt++) {
            asm volatile(
                "ldmatrix.sync.aligned.m8n8.x4.shared.b16 {%0,%1,%2,%3}, [%4];"
                : "=r"(a[mt][0]), "=r"(a[mt][1]), "=r"(a[mt][2]), "=r"(a[mt][3])
                : "r"(aoff[mt] + ks * 32));
        }
        #pragma unroll
        for (int np = 0; np < 4; np++) {
            asm volatile(
                "ldmatrix.sync.aligned.m8n8.x4.shared.b16 {%0,%1,%2,%3}, [%4];"
                : "=r"(b[np][0]), "=r"(b[np][1]), "=r"(b[np][2]), "=r"(b[np][3])
                : "r"(boff + (np * 16 * ASTRIDE) * 2 + ks * 32));
        }
        #pragma unroll
        for (int mt = 0; mt < 2; mt++)
            #pragma unroll
            for (int np = 0; np < 4; np++) {
                asm volatile(
                    "mma.sync.aligned.m16n8k16.row.col.f32.bf16.bf16.f32 "
                    "{%0,%1,%2,%3}, {%4,%5,%6,%7}, {%8,%9}, {%0,%1,%2,%3};\n"
                    : "+f"(acc[mt][2 * np][0]), "+f"(acc[mt][2 * np][1]),
                      "+f"(acc[mt][2 * np][2]), "+f"(acc[mt][2 * np][3])
                    : "r"(a[mt][0]), "r"(a[mt][1]), "r"(a[mt][2]), "r"(a[mt][3]),
                      "r"(b[np][0]), "r"(b[np][1]));
                asm volatile(
                    "mma.sync.aligned.m16n8k16.row.col.f32.bf16.bf16.f32 "
                    "{%0,%1,%2,%3}, {%4,%5,%6,%7}, {%8,%9}, {%0,%1,%2,%3};\n"
                    : "+f"(acc[mt][2 * np + 1][0]), "+f"(acc[mt][2 * np + 1][1]),
                      "+f"(acc[mt][2 * np + 1][2]), "+f"(acc[mt][2 * np + 1][3])
                    : "r"(a[mt][0]), "r"(a[mt][1]), "r"(a[mt][2]), "r"(a[mt][3]),
                      "r"(b[np][2]), "r"(b[np][3]));
            }
    }

    // Transposed epilogue, phase 1: raw acc -> smem (A/B space reused)
    __syncthreads();     // all fragment reads of As/Bs complete
    #pragma unroll
    for (int mt = 0; mt < 2; mt++) {
        int rla = m0 + mt * 16 + g;
        #pragma unroll
        for (int nt = 0; nt < 8; nt++) {
            int j = n0 + nt * 8 + 2 * t4;
            *(float2*)(epi + rla * EPI_STRIDE + j) =
                make_float2(acc[mt][nt][0], acc[mt][nt][1]);
            *(float2*)(epi + (rla + 8) * EPI_STRIDE + j) =
                make_float2(acc[mt][nt][2], acc[mt][nt][3]);
        }
    }
    __syncthreads();

    // Phase 2: warp-owns-row. seg broadcast, coalesced xm/bias, v4 .cs stores.
    #pragma unroll
    for (int i = 0; i < 16; i++) {
        int row = i * 8 + warp;
        int s = seg[r0 + row];                       // broadcast (1 addr/warp)
        const float* xmr = g_xm + (size_t)s * DIM;
        float4 ov = *(const float4*)(epi + row * EPI_STRIDE + lane * 4);
        float4 bv = *(const float4*)(bias + lane * 4);
        float4 xv = *(const float4*)(xmr + lane * 4);
        float4 o;
        o.x = ov.x + bv.x - xv.x;
        o.y = ov.y + bv.y - xv.y;
        o.z = ov.z + bv.z - xv.z;
        o.w = ov.w + bv.w - xv.w;
        stcs_f4(out + (size_t)(r0 + row) * DIM + lane * 4, o);
    }
}

// ---------------------------------------------------------------------------
extern "C" void kernel_launch(void* const* d_in, const int* in_sizes, int n_in,
                              void* d_out, int out_size) {
    const float* x   = (const float*)d_in[0];
    const int*   seg = (const int*)d_in[1];
    const float* GW = nullptr;
    const float* Gb = nullptr;
    const float* LW = nullptr;
    for (int i = 2; i < n_in; i++) {
        int s = in_sizes[i];
        if (s == DIM * DIM) { if (!GW) GW = (const float*)d_in[i]; else LW = (const float*)d_in[i]; }
        else if (s == DIM) { Gb = (const float*)d_in[i]; }
    }
    float* out = (float*)d_out;

    cudaFuncSetAttribute(k2_xm,   cudaFuncAttributeMaxDynamicSharedMemorySize, 74240);
    cudaFuncSetAttribute(k3_main, cudaFuncAttributeMaxDynamicSharedMemorySize, K3_SMEM);

    k0_init<<<2048, 256>>>(GW);
    k1_segsum<<<NROWS / 1024, 256>>>(x, seg);
    k2_xm<<<NSEG / 16, 128, 74240>>>(LW);
    k3_main<<<NROWS / 128, 256, K3_SMEM>>>(x, seg, Gb, out);
}